// round 5
// baseline (speedup 1.0000x reference)
#include <cuda_runtime.h>
#include <cuda_fp16.h>
#include <cstdint>

// VQ nearest-codebook quantization via warp-level mma.sync fp16-split GEMM.
// R4: 512 threads / 16 warps (4x4 grid, 32x32 warp tiles) to fix issue-limited
//     occupancy (R3: tensor=43%, issue=17%, 2 warps/SMSP).
// Inputs:  d_in[0] = z_e_x  [65536, 128] fp32,  d_in[1] = codebook [1024, 128] fp32
// Outputs (fp32): codes [65536*128] | flat_idx [65536] | idx [65536] | dist [65536]

#define C_DIM 128
#define BM    128

// ---- SMEM layout (bytes) ----
#define OFF_CSQ   0         // 1024 fp32 = 4096
#define OFF_XSQ   4096      // 128 fp32 = 512
#define OFF_REDV  4608      // 128*16 fp32 = 8192
#define OFF_REDI  12800     // 128*16 int  = 8192
#define OFF_A_H   24576     // 128x128 fp16 swizzled = 32768
#define OFF_A_L   57344     // 32768
#define OFF_B     90112     // 2 x 64KB (hi 32KB | lo 32KB)
#define B_BUF     65536
#define SMEM_TOTAL 221184

// Pre-split codebook, per-chunk SMEM image: [8 chunks][hi 32KB | lo 32KB]
__device__ uint4 g_B[8 * 4096];     // 512 KB
__device__ float g_csq[1024];

// ---------------- helpers ----------------
__device__ __forceinline__ uint32_t smem_u32(const void* p) {
    uint32_t a;
    asm("{ .reg .u64 t; cvta.to.shared.u64 t, %1; cvt.u32.u64 %0, t; }" : "=r"(a) : "l"(p));
    return a;
}
__device__ __forceinline__ void ldsm_x4(uint32_t* r, uint32_t addr) {
    asm volatile("ldmatrix.sync.aligned.m8n8.x4.shared.b16 {%0,%1,%2,%3}, [%4];"
                 : "=r"(r[0]), "=r"(r[1]), "=r"(r[2]), "=r"(r[3]) : "r"(addr));
}
__device__ __forceinline__ void mma16816(float* c, const uint32_t* a, const uint32_t* b) {
    asm volatile("mma.sync.aligned.m16n8k16.row.col.f32.f16.f16.f32 "
                 "{%0,%1,%2,%3}, {%4,%5,%6,%7}, {%8,%9}, {%0,%1,%2,%3};"
                 : "+f"(c[0]), "+f"(c[1]), "+f"(c[2]), "+f"(c[3])
                 : "r"(a[0]), "r"(a[1]), "r"(a[2]), "r"(a[3]), "r"(b[0]), "r"(b[1]));
}
#define CP_ASYNC16(dst, src) \
    asm volatile("cp.async.cg.shared.global [%0], [%1], 16;" :: "r"(dst), "l"(src))
#define CP_COMMIT() asm volatile("cp.async.commit_group;" ::: "memory")
#define CP_WAIT1()  asm volatile("cp.async.wait_group 1;" ::: "memory")

__device__ __forceinline__ void split2(float a, float b, uint32_t& hi, uint32_t& lo) {
    __half2 h = __floats2half2_rn(a, b);
    float2  f = __half22float2(h);
    __half2 l = __floats2half2_rn(a - f.x, b - f.y);
    hi = *reinterpret_cast<uint32_t*>(&h);
    lo = *reinterpret_cast<uint32_t*>(&l);
}

// ---------------- prep: split + swizzle codebook, csq ----------------
__global__ void prep_cb(const float* __restrict__ CB) {
    int t = blockIdx.x * blockDim.x + threadIdx.x;   // 0..2047
    int code = t >> 1, h = t & 1;
    const float4* src = reinterpret_cast<const float4*>(CB + (size_t)code * C_DIM + h * 64);
    char* base = (char*)g_B + (size_t)(code >> 7) * B_BUF;
    int r = code & 127;
    float s = 0.f;
    #pragma unroll
    for (int q = 0; q < 16; q += 2) {
        float4 v0 = src[q], v1 = src[q + 1];
        s += v0.x*v0.x + v0.y*v0.y + v0.z*v0.z + v0.w*v0.w
           + v1.x*v1.x + v1.y*v1.y + v1.z*v1.z + v1.w*v1.w;
        uint4 H, L;
        split2(v0.x, v0.y, H.x, L.x); split2(v0.z, v0.w, H.y, L.y);
        split2(v1.x, v1.y, H.z, L.z); split2(v1.z, v1.w, H.w, L.w);
        int cg = h * 8 + (q >> 1);                       // 16B chunk index 0..15
        uint32_t off = (uint32_t)(r * 256 + ((cg ^ (r & 7)) << 4));
        *reinterpret_cast<uint4*>(base + off) = H;           // hi at +0
        *reinterpret_cast<uint4*>(base + 32768 + off) = L;   // lo at +32KB
    }
    s += __shfl_xor_sync(0xffffffffu, s, 1);
    if (!h) g_csq[code] = s;
}

// ---------------- main kernel ----------------
__device__ __forceinline__ void issue_chunk(uint32_t sb, int buf, int chunk, int tid) {
    const char* src = (const char*)g_B + (size_t)chunk * B_BUF + tid * 16;
    uint32_t dst = sb + OFF_B + buf * B_BUF + tid * 16;
    #pragma unroll
    for (int i = 0; i < 8; i++)
        CP_ASYNC16(dst + i * 8192, src + i * 8192);
}

__global__ __launch_bounds__(512, 1)
void vq_main(const float* __restrict__ X, const float* __restrict__ CB,
             float* __restrict__ out_codes, float* __restrict__ out_fidx,
             float* __restrict__ out_idx,   float* __restrict__ out_dist,
             int n_codes)
{
    extern __shared__ char smem[];
    const uint32_t sb = smem_u32(smem);
    const int tid = threadIdx.x, lane = tid & 31, wid = tid >> 5;
    const int warpM = wid >> 2, warpN = wid & 3;      // 4 x 4 warp grid
    const int block_row = blockIdx.x * BM;
    const int NC = n_codes >> 7;    // chunks of 128 codes

    issue_chunk(sb, 0, 0, tid);
    CP_COMMIT();

    // csq -> SMEM
    for (int i = tid; i < n_codes; i += 512)
        reinterpret_cast<float*>(smem + OFF_CSQ)[i] = g_csq[i];

    // A tile: fp32 rows -> fp16 hi/lo, swizzled; fused xsq. 4 threads per row.
    {
        const int r = tid >> 2, qp = tid & 3;
        const float4* src = reinterpret_cast<const float4*>(
            X + (size_t)(block_row + r) * C_DIM + qp * 32);
        float s = 0.f;
        #pragma unroll
        for (int q = 0; q < 8; q += 2) {
            float4 v0 = src[q], v1 = src[q + 1];
            s += v0.x*v0.x + v0.y*v0.y + v0.z*v0.z + v0.w*v0.w
               + v1.x*v1.x + v1.y*v1.y + v1.z*v1.z + v1.w*v1.w;
            uint4 H, L;
            split2(v0.x, v0.y, H.x, L.x); split2(v0.z, v0.w, H.y, L.y);
            split2(v1.x, v1.y, H.z, L.z); split2(v1.z, v1.w, H.w, L.w);
            int cg = qp * 4 + (q >> 1);
            uint32_t off = (uint32_t)(r * 256 + ((cg ^ (r & 7)) << 4));
            *reinterpret_cast<uint4*>(smem + OFF_A_H + off) = H;
            *reinterpret_cast<uint4*>(smem + OFF_A_L + off) = L;
        }
        s += __shfl_xor_sync(0xffffffffu, s, 1);
        s += __shfl_xor_sync(0xffffffffu, s, 2);
        if (!qp) reinterpret_cast<float*>(smem + OFF_XSQ)[r] = s;
    }

    if (NC > 1) issue_chunk(sb, 1, 1, tid);
    CP_COMMIT();
    __syncthreads();

    // per-thread ldmatrix address constants (32x32 warp tile)
    const uint32_t aOff   = (uint32_t)((warpM * 32 + (lane & 15)) * 256);
    const uint32_t bOff   = (uint32_t)((warpN * 32 + (lane & 7) + ((lane >> 4) << 3)) * 256);
    const uint32_t sw     = (uint32_t)(lane & 7);
    const uint32_t achsel = (uint32_t)(lane >> 4);
    const uint32_t bchsel = (uint32_t)((lane >> 3) & 1);

    float bestv[4];
    int   besti[4];
    #pragma unroll
    for (int i = 0; i < 4; i++) { bestv[i] = 3.4e38f; besti[i] = 0; }

    for (int c = 0; c < NC; c++) {
        CP_WAIT1();
        __syncthreads();

        const int buf = c & 1;
        float acc[2][4][4];
        #pragma unroll
        for (int mi = 0; mi < 2; mi++)
            #pragma unroll
            for (int ni = 0; ni < 4; ni++)
                #pragma unroll
                for (int j = 0; j < 4; j++) acc[mi][ni][j] = 0.f;

        #pragma unroll
        for (int pass = 0; pass < 3; pass++) {
            const uint32_t Ab = sb + (pass == 2 ? OFF_A_L : OFF_A_H) + aOff;
            const uint32_t Bb = sb + OFF_B + buf * B_BUF + (pass == 1 ? 32768 : 0) + bOff;
            #pragma unroll
            for (int ks = 0; ks < 8; ks++) {
                const uint32_t ach = (((uint32_t)(2 * ks) + achsel) ^ sw) << 4;
                const uint32_t bch = (((uint32_t)(2 * ks) + bchsel) ^ sw) << 4;
                uint32_t a[2][4], b[2][4];
                ldsm_x4(a[0], Ab + ach);
                ldsm_x4(a[1], Ab + 4096 + ach);
                ldsm_x4(b[0], Bb + bch);
                ldsm_x4(b[1], Bb + 4096 + bch);
                #pragma unroll
                for (int mi = 0; mi < 2; mi++)
                    #pragma unroll
                    for (int ni = 0; ni < 4; ni++)
                        mma16816(acc[mi][ni], a[mi], &b[ni >> 1][(ni & 1) * 2]);
            }
        }

        // fold: argmin of csq - 2*dot (strict <, ascending cols -> first-index)
        {
            const float* csqs = reinterpret_cast<const float*>(smem + OFF_CSQ)
                                + c * 128 + warpN * 32;
            #pragma unroll
            for (int mi = 0; mi < 2; mi++) {
                #pragma unroll
                for (int ni = 0; ni < 4; ni++) {
                    const int col = ni * 8 + (lane & 3) * 2;
                    const float cs0 = csqs[col], cs1 = csqs[col + 1];
                    const int gcol = c * 128 + warpN * 32 + col;
                    float v0 = fmaf(-2.f, acc[mi][ni][0], cs0);
                    float v1 = fmaf(-2.f, acc[mi][ni][1], cs1);
                    float v2 = fmaf(-2.f, acc[mi][ni][2], cs0);
                    float v3 = fmaf(-2.f, acc[mi][ni][3], cs1);
                    const int p0 = mi * 2, p1 = mi * 2 + 1;
                    if (v0 < bestv[p0]) { bestv[p0] = v0; besti[p0] = gcol; }
                    if (v1 < bestv[p0]) { bestv[p0] = v1; besti[p0] = gcol + 1; }
                    if (v2 < bestv[p1]) { bestv[p1] = v2; besti[p1] = gcol; }
                    if (v3 < bestv[p1]) { bestv[p1] = v3; besti[p1] = gcol + 1; }
                }
            }
        }

        __syncthreads();
        if (c + 2 < NC) issue_chunk(sb, buf, c + 2, tid);
        CP_COMMIT();                 // commit even when empty: keeps group count aligned
    }

    // write per-thread winners: rows x 16 slots
    #pragma unroll
    for (int mi = 0; mi < 2; mi++)
        #pragma unroll
        for (int rh = 0; rh < 2; rh++) {
            const int rowl = warpM * 32 + mi * 16 + rh * 8 + (lane >> 2);
            const int slot = warpN * 4 + (lane & 3);
            reinterpret_cast<float*>(smem + OFF_REDV)[rowl * 16 + slot] = bestv[mi * 2 + rh];
            reinterpret_cast<int*>(smem + OFF_REDI)[rowl * 16 + slot]   = besti[mi * 2 + rh];
        }
    __syncthreads();

    if (tid < BM) {
        const float* rv = reinterpret_cast<const float*>(smem + OFF_REDV) + tid * 16;
        const int*   ri = reinterpret_cast<const int*>(smem + OFF_REDI) + tid * 16;
        float bv = rv[0]; int bi = ri[0];
        #pragma unroll
        for (int s = 1; s < 16; s++) {
            float v = rv[s]; int ii = ri[s];
            if (v < bv || (v == bv && ii < bi)) { bv = v; bi = ii; }
        }
        const int row = block_row + tid;
        if (out_fidx) {
            float fbi = (float)bi;
            out_fidx[row] = fbi;
            out_idx[row]  = fbi;
            out_dist[row] = reinterpret_cast<float*>(smem + OFF_XSQ)[tid] + bv;
        }
        reinterpret_cast<int*>(smem + OFF_REDI)[tid * 16] = bi;  // stash for gather
    }
    __syncthreads();

    // codes gather: 4 threads per row, 32 floats (8 float4) each
    {
        const int r = tid >> 2, qq = tid & 3;
        const int code = reinterpret_cast<int*>(smem + OFF_REDI)[r * 16];
        const float4* src = reinterpret_cast<const float4*>(CB + (size_t)code * C_DIM) + qq * 8;
        float4* dst = reinterpret_cast<float4*>(out_codes + (size_t)(block_row + r) * C_DIM) + qq * 8;
        #pragma unroll
        for (int q = 0; q < 8; q++) dst[q] = src[q];
    }
}

extern "C" void kernel_launch(void* const* d_in, const int* in_sizes, int n_in,
                              void* d_out, int out_size)
{
    const float* X  = (const float*)d_in[0];
    const float* CB = (const float*)d_in[1];
    float* out = (float*)d_out;

    const int n_rows  = in_sizes[0] / C_DIM;   // 65536
    const int n_codes = in_sizes[1] / C_DIM;   // 1024

    size_t codes_n = (size_t)n_rows * C_DIM;
    bool extras = ((size_t)out_size >= codes_n + 3 * (size_t)n_rows);

    float* out_codes = out;
    float* out_fidx  = extras ? out + codes_n : nullptr;
    float* out_idx   = extras ? out + codes_n + n_rows : nullptr;
    float* out_dist  = extras ? out + codes_n + 2 * (size_t)n_rows : nullptr;

    static bool attr_set = false;
    if (!attr_set) {
        cudaFuncSetAttribute(vq_main, cudaFuncAttributeMaxDynamicSharedMemorySize, SMEM_TOTAL);
        attr_set = true;
    }

    prep_cb<<<(n_codes * 2) / 256, 256>>>(CB);
    vq_main<<<n_rows / BM, 512, SMEM_TOTAL>>>(X, CB, out_codes, out_fidx,
                                              out_idx, out_dist, n_codes);
}